// round 1
// baseline (speedup 1.0000x reference)
#include <cuda_runtime.h>
#include <cstdint>

#define BATCH 4096
#define NST   512
#define IO    16
#define DS    32
#define PTOT  8192
#define THREADS 256
#define ROWS_PER_CTA 32

// ---------- cp.async helpers ----------
__device__ __forceinline__ void cpasync16(float4* s, const float4* g) {
    uint32_t sa = (uint32_t)__cvta_generic_to_shared(s);
    asm volatile("cp.async.cg.shared.global [%0], [%1], 16;" :: "r"(sa), "l"(g));
}
__device__ __forceinline__ void cpcommit() { asm volatile("cp.async.commit_group;"); }
template<int N> __device__ __forceinline__ void cpwait() {
    asm volatile("cp.async.wait_group %0;" :: "n"(N));
}

// Weight smem layout (in float4 units), per stage buffer of 576 float4:
//   causal: A [0,256)  B [256,384)  C [384,512)  D [512,576)
//   anti:   E [0,256)  F [256,384)  G [384,512)
__device__ __forceinline__ void load_causal_stage(float4* dst, int st, int tid,
                                                  const float4* A4, const float4* B4,
                                                  const float4* C4, const float4* D4) {
    for (int i = tid; i < 576; i += THREADS) {
        const float4* src;
        if      (i < 256) src = A4 + st * 256 + i;
        else if (i < 384) src = B4 + st * 128 + (i - 256);
        else if (i < 512) src = C4 + st * 128 + (i - 384);
        else              src = D4 + st * 64  + (i - 512);
        cpasync16(dst + i, src);
    }
}
__device__ __forceinline__ void load_anti_stage(float4* dst, int st, int tid,
                                                const float4* E4, const float4* F4,
                                                const float4* G4) {
    for (int i = tid; i < 512; i += THREADS) {
        const float4* src;
        if      (i < 256) src = E4 + st * 256 + i;
        else if (i < 384) src = F4 + st * 128 + (i - 256);
        else              src = G4 + st * 128 + (i - 384);
        cpasync16(dst + i, src);
    }
}

__global__ __launch_bounds__(THREADS)
void semisep_kernel(const float* __restrict__ U,
                    const float4* __restrict__ A4, const float4* __restrict__ B4,
                    const float4* __restrict__ C4, const float4* __restrict__ D4,
                    const float4* __restrict__ E4, const float4* __restrict__ F4,
                    const float4* __restrict__ G4,
                    const float*  __restrict__ bias,
                    float* __restrict__ out) {
    __shared__ float4 sw[2 * 576];

    const int tid = threadIdx.x;
    const int p   = tid & 7;        // 8 threads per row; lane segment of 8
    const int r   = tid >> 3;       // row within CTA
    const int row = blockIdx.x * ROWS_PER_CTA + r;

    const float* urow = U   + (size_t)row * PTOT;
    float*       orow = out + (size_t)row * PTOT;

    // =========================== CAUSAL (forward) ===========================
    load_causal_stage(sw,       0, tid, A4, B4, C4, D4); cpcommit();
    load_causal_stage(sw + 576, 1, tid, A4, B4, C4, D4); cpcommit();

    // rotated state: xr[m] = x[(m + 4p) % 32]
    float xr[32];
#pragma unroll
    for (int m = 0; m < 32; ++m) xr[m] = 0.f;

    for (int k = 0; k < NST; ++k) {
        cpwait<1>();
        __syncthreads();
        const float4* w = sw + (k & 1) * 576;

        // u, rotated: ur[m] = u[(m + 4p) % 16]
        float ur[16];
        const float4* up = (const float4*)(urow + k * IO);
#pragma unroll
        for (int mm = 0; mm < 4; ++mm) {
            float4 v = up[(mm + p) & 3];
            ur[4*mm+0] = v.x; ur[4*mm+1] = v.y; ur[4*mm+2] = v.z; ur[4*mm+3] = v.w;
        }

        // x' parts: this thread owns rows i = 4p + ii of x'
        float acc[4] = {0.f, 0.f, 0.f, 0.f};
#pragma unroll
        for (int jj = 0; jj < 8; ++jj) {
            int s = (jj + p) & 7;
#pragma unroll
            for (int ii = 0; ii < 4; ++ii) {
                float4 a = w[(4*p + ii) * 8 + s];
                acc[ii] += a.x * xr[4*jj+0] + a.y * xr[4*jj+1]
                         + a.z * xr[4*jj+2] + a.w * xr[4*jj+3];
            }
        }
#pragma unroll
        for (int jj = 0; jj < 4; ++jj) {
            int s = (jj + p) & 3;
#pragma unroll
            for (int ii = 0; ii < 4; ++ii) {
                float4 b = w[256 + (4*p + ii) * 4 + s];
                acc[ii] += b.x * ur[4*jj+0] + b.y * ur[4*jj+1]
                         + b.z * ur[4*jj+2] + b.w * ur[4*jj+3];
            }
        }

        // y parts: rows iy = 2p, 2p+1;  y = C x + D u + bias
        float2 bv = *(const float2*)(bias + k * IO + 2 * p);
        float y0 = bv.x, y1 = bv.y;
#pragma unroll
        for (int jj = 0; jj < 8; ++jj) {
            int s = (jj + p) & 7;
            float4 c0 = w[384 + (2*p + 0) * 8 + s];
            float4 c1 = w[384 + (2*p + 1) * 8 + s];
            y0 += c0.x * xr[4*jj+0] + c0.y * xr[4*jj+1] + c0.z * xr[4*jj+2] + c0.w * xr[4*jj+3];
            y1 += c1.x * xr[4*jj+0] + c1.y * xr[4*jj+1] + c1.z * xr[4*jj+2] + c1.w * xr[4*jj+3];
        }
#pragma unroll
        for (int jj = 0; jj < 4; ++jj) {
            int s = (jj + p) & 3;
            float4 d0 = w[512 + (2*p + 0) * 4 + s];
            float4 d1 = w[512 + (2*p + 1) * 4 + s];
            y0 += d0.x * ur[4*jj+0] + d0.y * ur[4*jj+1] + d0.z * ur[4*jj+2] + d0.w * ur[4*jj+3];
            y1 += d1.x * ur[4*jj+0] + d1.y * ur[4*jj+1] + d1.z * ur[4*jj+2] + d1.w * ur[4*jj+3];
        }
        *(float2*)(orow + k * IO + 2 * p) = make_float2(y0, y1);

        // exchange x' among the 8 owner threads into rotated layout
#pragma unroll
        for (int mm = 0; mm < 8; ++mm) {
            int srcp = (mm + p) & 7;
            xr[4*mm+0] = __shfl_sync(0xffffffffu, acc[0], srcp, 8);
            xr[4*mm+1] = __shfl_sync(0xffffffffu, acc[1], srcp, 8);
            xr[4*mm+2] = __shfl_sync(0xffffffffu, acc[2], srcp, 8);
            xr[4*mm+3] = __shfl_sync(0xffffffffu, acc[3], srcp, 8);
        }

        __syncthreads();
        if (k + 2 < NST)
            load_causal_stage(sw + (k & 1) * 576, k + 2, tid, A4, B4, C4, D4);
        cpcommit();
    }

    // ========================= ANTICAUSAL (reverse) =========================
    // stage k lives in buffer (k & 1), same convention as causal.
    load_anti_stage(sw + 576, NST - 1, tid, E4, F4, G4); cpcommit();
    load_anti_stage(sw,       NST - 2, tid, E4, F4, G4); cpcommit();

    float zr[32];
#pragma unroll
    for (int m = 0; m < 32; ++m) zr[m] = 0.f;

    for (int k = NST - 1; k >= 0; --k) {
        cpwait<1>();
        __syncthreads();
        const float4* w = sw + (k & 1) * 576;

        float ur[16];
        const float4* up = (const float4*)(urow + k * IO);
#pragma unroll
        for (int mm = 0; mm < 4; ++mm) {
            float4 v = up[(mm + p) & 3];
            ur[4*mm+0] = v.x; ur[4*mm+1] = v.y; ur[4*mm+2] = v.z; ur[4*mm+3] = v.w;
        }

        // y += G z   (z BEFORE update)
        float2 yv = *(const float2*)(orow + k * IO + 2 * p);
        float y0 = yv.x, y1 = yv.y;
#pragma unroll
        for (int jj = 0; jj < 8; ++jj) {
            int s = (jj + p) & 7;
            float4 g0 = w[384 + (2*p + 0) * 8 + s];
            float4 g1 = w[384 + (2*p + 1) * 8 + s];
            y0 += g0.x * zr[4*jj+0] + g0.y * zr[4*jj+1] + g0.z * zr[4*jj+2] + g0.w * zr[4*jj+3];
            y1 += g1.x * zr[4*jj+0] + g1.y * zr[4*jj+1] + g1.z * zr[4*jj+2] + g1.w * zr[4*jj+3];
        }

        // z' = E z + F u
        float acc[4] = {0.f, 0.f, 0.f, 0.f};
#pragma unroll
        for (int jj = 0; jj < 8; ++jj) {
            int s = (jj + p) & 7;
#pragma unroll
            for (int ii = 0; ii < 4; ++ii) {
                float4 e = w[(4*p + ii) * 8 + s];
                acc[ii] += e.x * zr[4*jj+0] + e.y * zr[4*jj+1]
                         + e.z * zr[4*jj+2] + e.w * zr[4*jj+3];
            }
        }
#pragma unroll
        for (int jj = 0; jj < 4; ++jj) {
            int s = (jj + p) & 3;
#pragma unroll
            for (int ii = 0; ii < 4; ++ii) {
                float4 f = w[256 + (4*p + ii) * 4 + s];
                acc[ii] += f.x * ur[4*jj+0] + f.y * ur[4*jj+1]
                         + f.z * ur[4*jj+2] + f.w * ur[4*jj+3];
            }
        }

        *(float2*)(orow + k * IO + 2 * p) = make_float2(y0, y1);

#pragma unroll
        for (int mm = 0; mm < 8; ++mm) {
            int srcp = (mm + p) & 7;
            zr[4*mm+0] = __shfl_sync(0xffffffffu, acc[0], srcp, 8);
            zr[4*mm+1] = __shfl_sync(0xffffffffu, acc[1], srcp, 8);
            zr[4*mm+2] = __shfl_sync(0xffffffffu, acc[2], srcp, 8);
            zr[4*mm+3] = __shfl_sync(0xffffffffu, acc[3], srcp, 8);
        }

        __syncthreads();
        if (k - 2 >= 0)
            load_anti_stage(sw + (k & 1) * 576, k - 2, tid, E4, F4, G4);
        cpcommit();
    }
}

extern "C" void kernel_launch(void* const* d_in, const int* in_sizes, int n_in,
                              void* d_out, int out_size) {
    const float*  U    = (const float*) d_in[0];
    const float4* A4   = (const float4*)d_in[1];
    const float4* B4   = (const float4*)d_in[2];
    const float4* C4   = (const float4*)d_in[3];
    const float4* D4   = (const float4*)d_in[4];
    const float4* E4   = (const float4*)d_in[5];
    const float4* F4   = (const float4*)d_in[6];
    const float4* G4   = (const float4*)d_in[7];
    const float*  bias = (const float*) d_in[8];
    float* out = (float*)d_out;

    semisep_kernel<<<BATCH / ROWS_PER_CTA, THREADS>>>(
        U, A4, B4, C4, D4, E4, F4, G4, bias, out);
}

// round 2
// speedup vs baseline: 1.9610x; 1.9610x over previous
#include <cuda_runtime.h>
#include <cstdint>

#define BATCH 4096
#define NST   512
#define IO    16
#define DS    32
#define PTOT  8192
#define NCH   32
#define LCH   16   // stages per chunk

// ---------------- scratch (device globals; no mallocs allowed) ----------------
__device__ float g_xloc[2][BATCH][NCH][DS];   // local chunk-exit states
__device__ float g_xin [2][BATCH][NCH][DS];   // chunk-entry states
__device__ float g_M   [2][NST][IO*DS];       // M_k = C_k Phi_k ; N_k = G_k Psi_k
__device__ float g_P   [2][NCH][DS*DS];       // chunk propagators
__device__ float g_ya  [BATCH*PTOT];          // anticausal local y

// ---------------- cp.async helpers ----------------
__device__ __forceinline__ void cpasync16(void* s, const void* g) {
    uint32_t sa = (uint32_t)__cvta_generic_to_shared(s);
    asm volatile("cp.async.cg.shared.global [%0], [%1], 16;" :: "r"(sa), "l"(g));
}
__device__ __forceinline__ void cpcommit() { asm volatile("cp.async.commit_group;"); }
template<int N> __device__ __forceinline__ void cpwait() {
    asm volatile("cp.async.wait_group %0;" :: "n"(N));
}

// =====================================================================
// Precompute: per (dir, chunk): prefix transfer matrices + M/N + P.
//   causal:  Phi_{c0}=I; M_k=C_k Phi; Phi<-A_k Phi;  P_c = final Phi
//   anti:    Psi_{top}=I; N_k=G_k Psi; Psi<-E_k Psi; P^a_c = final Psi
// =====================================================================
__global__ void precompute_kernel(const float* __restrict__ A, const float* __restrict__ C,
                                  const float* __restrict__ E, const float* __restrict__ G) {
    __shared__ float Phi[2][DS*DS];
    const int tid = threadIdx.x;
    const int c = blockIdx.x, d = blockIdx.y;

    for (int i = tid; i < DS*DS; i += 256) Phi[0][i] = ((i >> 5) == (i & 31)) ? 1.f : 0.f;
    __syncthreads();

    int pb = 0;
    for (int t = 0; t < LCH; ++t) {
        const int k = (d == 0) ? (c*LCH + t) : (c*LCH + LCH-1 - t);
        const float* W1 = (d == 0) ? (C + k*IO*DS) : (G + k*IO*DS);   // 16x32
        const float* W2 = (d == 0) ? (A + k*DS*DS) : (E + k*DS*DS);   // 32x32

        // M_k = W1 * Phi  (512 outputs, 2 per thread)
        float* Mk = &g_M[d][k][0];
        for (int e = tid; e < IO*DS; e += 256) {
            const int i = e >> 5, j = e & 31;
            float acc = 0.f;
#pragma unroll
            for (int l = 0; l < DS; ++l) acc += W1[i*DS + l] * Phi[pb][l*DS + j];
            Mk[e] = acc;
        }
        // Phi_new = W2 * Phi  (1024 outputs, 4 per thread)
        for (int e = tid; e < DS*DS; e += 256) {
            const int i = e >> 5, j = e & 31;
            float acc = 0.f;
#pragma unroll
            for (int l = 0; l < DS; ++l) acc += W2[i*DS + l] * Phi[pb][l*DS + j];
            Phi[pb^1][e] = acc;
        }
        __syncthreads();
        pb ^= 1;
    }
    for (int e = tid; e < DS*DS; e += 256) g_P[d][c][e] = Phi[pb][e];
}

// =====================================================================
// Phase A: local chunk scans with zero initial state. One thread per row.
// CTA = (rowblock of 256, chunk, dir). Weights double-buffered via cp.async.
// =====================================================================
#define CSZ 2320   // causal stage floats: A 0..1024, B 1024..1536, C 1536..2048, D 2048..2304, bias 2304..2320
#define ASZ 2048   // anti stage floats:   E 0..1024, F 1024..1536, G 1536..2048

__global__ __launch_bounds__(256, 2)
void phaseA_kernel(const float* __restrict__ U,
                   const float* __restrict__ A, const float* __restrict__ B,
                   const float* __restrict__ C, const float* __restrict__ D,
                   const float* __restrict__ E, const float* __restrict__ F,
                   const float* __restrict__ G, const float* __restrict__ bias,
                   float* __restrict__ out) {
    __shared__ float sw[2][CSZ];

    const int tid = threadIdx.x;
    const int c = blockIdx.y, d = blockIdx.z;
    const int row = blockIdx.x * 256 + tid;
    const int k0 = c * LCH;

    auto load_stage = [&](float* dst, int k) {
        if (d == 0) {
            for (int i = tid; i < 580; i += 256) {
                const float4* src;
                if      (i < 256) src = (const float4*)(A + (size_t)k*1024) + i;
                else if (i < 384) src = (const float4*)(B + (size_t)k*512)  + (i-256);
                else if (i < 512) src = (const float4*)(C + (size_t)k*512)  + (i-384);
                else if (i < 576) src = (const float4*)(D + (size_t)k*256)  + (i-512);
                else              src = (const float4*)(bias + (size_t)k*16) + (i-576);
                cpasync16((float4*)dst + i, src);
            }
        } else {
            for (int i = tid; i < 512; i += 256) {
                const float4* src;
                if      (i < 256) src = (const float4*)(E + (size_t)k*1024) + i;
                else if (i < 384) src = (const float4*)(F + (size_t)k*512)  + (i-256);
                else              src = (const float4*)(G + (size_t)k*512)  + (i-384);
                cpasync16((float4*)dst + i, src);
            }
        }
    };
    auto stage_k = [&](int t) { return (d == 0) ? (k0 + t) : (k0 + LCH-1 - t); };

    load_stage(sw[0], stage_k(0)); cpcommit();
    load_stage(sw[1], stage_k(1)); cpcommit();

    float x[DS];
#pragma unroll
    for (int i = 0; i < DS; ++i) x[i] = 0.f;

#pragma unroll 1
    for (int t = 0; t < LCH; ++t) {
        cpwait<1>();
        __syncthreads();
        const float* w = sw[t & 1];
        const int k = stage_k(t);
        const size_t off = (size_t)row * PTOT + (size_t)k * IO;

        float u[IO];
        {
            const float4* up = (const float4*)(U + off);
#pragma unroll
            for (int m = 0; m < 4; ++m) {
                float4 v = up[m];
                u[4*m] = v.x; u[4*m+1] = v.y; u[4*m+2] = v.z; u[4*m+3] = v.w;
            }
        }

        if (d == 0) {
            // y = C x + D u + bias
            float y[IO];
#pragma unroll
            for (int i = 0; i < IO; ++i) {
                float acc = w[2304 + i];
#pragma unroll
                for (int j = 0; j < 8; ++j) {
                    float4 cv = ((const float4*)(w + 1536))[i*8 + j];
                    acc += cv.x*x[4*j] + cv.y*x[4*j+1] + cv.z*x[4*j+2] + cv.w*x[4*j+3];
                }
#pragma unroll
                for (int j = 0; j < 4; ++j) {
                    float4 dv = ((const float4*)(w + 2048))[i*4 + j];
                    acc += dv.x*u[4*j] + dv.y*u[4*j+1] + dv.z*u[4*j+2] + dv.w*u[4*j+3];
                }
                y[i] = acc;
            }
            float4* op = (float4*)(out + off);
#pragma unroll
            for (int m = 0; m < 4; ++m)
                op[m] = make_float4(y[4*m], y[4*m+1], y[4*m+2], y[4*m+3]);

            // x' = A x + B u
            float xn[DS];
#pragma unroll
            for (int i = 0; i < DS; ++i) {
                float acc = 0.f;
#pragma unroll
                for (int j = 0; j < 8; ++j) {
                    float4 av = ((const float4*)w)[i*8 + j];
                    acc += av.x*x[4*j] + av.y*x[4*j+1] + av.z*x[4*j+2] + av.w*x[4*j+3];
                }
#pragma unroll
                for (int j = 0; j < 4; ++j) {
                    float4 bv = ((const float4*)(w + 1024))[i*4 + j];
                    acc += bv.x*u[4*j] + bv.y*u[4*j+1] + bv.z*u[4*j+2] + bv.w*u[4*j+3];
                }
                xn[i] = acc;
            }
#pragma unroll
            for (int i = 0; i < DS; ++i) x[i] = xn[i];
        } else {
            // y = G z (z before update)
            float y[IO];
#pragma unroll
            for (int i = 0; i < IO; ++i) {
                float acc = 0.f;
#pragma unroll
                for (int j = 0; j < 8; ++j) {
                    float4 gv = ((const float4*)(w + 1536))[i*8 + j];
                    acc += gv.x*x[4*j] + gv.y*x[4*j+1] + gv.z*x[4*j+2] + gv.w*x[4*j+3];
                }
                y[i] = acc;
            }
            float4* op = (float4*)(g_ya + off);
#pragma unroll
            for (int m = 0; m < 4; ++m)
                op[m] = make_float4(y[4*m], y[4*m+1], y[4*m+2], y[4*m+3]);

            // z' = E z + F u
            float xn[DS];
#pragma unroll
            for (int i = 0; i < DS; ++i) {
                float acc = 0.f;
#pragma unroll
                for (int j = 0; j < 8; ++j) {
                    float4 ev = ((const float4*)w)[i*8 + j];
                    acc += ev.x*x[4*j] + ev.y*x[4*j+1] + ev.z*x[4*j+2] + ev.w*x[4*j+3];
                }
#pragma unroll
                for (int j = 0; j < 4; ++j) {
                    float4 fv = ((const float4*)(w + 1024))[i*4 + j];
                    acc += fv.x*u[4*j] + fv.y*u[4*j+1] + fv.z*u[4*j+2] + fv.w*u[4*j+3];
                }
                xn[i] = acc;
            }
#pragma unroll
            for (int i = 0; i < DS; ++i) x[i] = xn[i];
        }

        __syncthreads();
        if (t + 2 < LCH) load_stage(sw[t & 1], stage_k(t + 2));
        cpcommit();
    }

    // store chunk-exit local state
    float4* xo = (float4*)&g_xloc[d][row][c][0];
#pragma unroll
    for (int m = 0; m < 8; ++m)
        xo[m] = make_float4(x[4*m], x[4*m+1], x[4*m+2], x[4*m+3]);
}

// =====================================================================
// Phase B: sequential chunk recombination per row. One warp per (row, dir).
//   x_in(first)=0; store x_in(c); x_in(next) = P_c x_in(c) + xloc(c)
// =====================================================================
__global__ __launch_bounds__(256)
void phaseB_kernel() {
    __shared__ float sP[DS*DS];
    const int tid = threadIdx.x, lane = tid & 31, wp = tid >> 5;
    const int d = blockIdx.x >> 9;                  // 512 CTAs per direction
    const int row = ((blockIdx.x & 511) << 3) + wp;

    float x = 0.f;
    for (int ci = 0; ci < NCH; ++ci) {
        const int c = (d == 0) ? ci : (NCH-1 - ci);
        __syncthreads();
        for (int i = tid; i < DS*DS; i += 256) sP[i] = g_P[d][c][i];
        __syncthreads();

        g_xin[d][row][c][lane] = x;
        float acc = g_xloc[d][row][c][lane];
        const float* pr = &sP[lane * DS];
#pragma unroll
        for (int j = 0; j < DS; ++j) {
            const int jj = (j + lane) & 31;          // bank-conflict-free stagger
            acc += pr[jj] * __shfl_sync(0xffffffffu, x, jj);
        }
        x = acc;
    }
}

// =====================================================================
// Fixup: out = y_c(+bias) + y_a_local + M_k x_in + N_k z_in
// CTA = (rowblock 256, chunk); M/N double-buffered via cp.async.
// =====================================================================
__global__ __launch_bounds__(256, 2)
void fixup_kernel(float* __restrict__ out) {
    __shared__ float sm[2][2*IO*DS];   // M_k (512) | N_k (512)
    const int tid = threadIdx.x;
    const int c = blockIdx.y;
    const int row = blockIdx.x * 256 + tid;
    const int k0 = c * LCH;

    auto load_mn = [&](float* dst, int k) {
        if (tid < 128) cpasync16((float4*)dst + tid, (const float4*)&g_M[0][k][0] + tid);
        else           cpasync16((float4*)dst + tid, (const float4*)&g_M[1][k][0] + (tid-128));
    };
    load_mn(sm[0], k0);     cpcommit();
    load_mn(sm[1], k0 + 1); cpcommit();

    float xin[DS], zin[DS];
    {
        const float4* xi = (const float4*)&g_xin[0][row][c][0];
        const float4* zi = (const float4*)&g_xin[1][row][c][0];
#pragma unroll
        for (int m = 0; m < 8; ++m) {
            float4 a = xi[m]; xin[4*m]=a.x; xin[4*m+1]=a.y; xin[4*m+2]=a.z; xin[4*m+3]=a.w;
            float4 b = zi[m]; zin[4*m]=b.x; zin[4*m+1]=b.y; zin[4*m+2]=b.z; zin[4*m+3]=b.w;
        }
    }

#pragma unroll 1
    for (int s = 0; s < LCH; ++s) {
        cpwait<1>();
        __syncthreads();
        const float* M = sm[s & 1];
        const float* N = M + IO*DS;
        const int k = k0 + s;
        const size_t off = (size_t)row * PTOT + (size_t)k * IO;

        float y[IO];
        {
            const float4* op = (const float4*)(out + off);
            const float4* ap = (const float4*)(g_ya + off);
#pragma unroll
            for (int m = 0; m < 4; ++m) {
                float4 a = op[m], b = ap[m];
                y[4*m]=a.x+b.x; y[4*m+1]=a.y+b.y; y[4*m+2]=a.z+b.z; y[4*m+3]=a.w+b.w;
            }
        }
#pragma unroll
        for (int i = 0; i < IO; ++i) {
            float acc = y[i];
#pragma unroll
            for (int j = 0; j < 8; ++j) {
                float4 mv = ((const float4*)M)[i*8 + j];
                acc += mv.x*xin[4*j] + mv.y*xin[4*j+1] + mv.z*xin[4*j+2] + mv.w*xin[4*j+3];
                float4 nv = ((const float4*)N)[i*8 + j];
                acc += nv.x*zin[4*j] + nv.y*zin[4*j+1] + nv.z*zin[4*j+2] + nv.w*zin[4*j+3];
            }
            y[i] = acc;
        }
        float4* op = (float4*)(out + off);
#pragma unroll
        for (int m = 0; m < 4; ++m)
            op[m] = make_float4(y[4*m], y[4*m+1], y[4*m+2], y[4*m+3]);

        __syncthreads();
        if (s + 2 < LCH) load_mn(sm[s & 1], k0 + s + 2);
        cpcommit();
    }
}

// =====================================================================
extern "C" void kernel_launch(void* const* d_in, const int* in_sizes, int n_in,
                              void* d_out, int out_size) {
    const float* U    = (const float*)d_in[0];
    const float* A    = (const float*)d_in[1];
    const float* B    = (const float*)d_in[2];
    const float* C    = (const float*)d_in[3];
    const float* D    = (const float*)d_in[4];
    const float* E    = (const float*)d_in[5];
    const float* F    = (const float*)d_in[6];
    const float* G    = (const float*)d_in[7];
    const float* bias = (const float*)d_in[8];
    float* out = (float*)d_out;

    precompute_kernel<<<dim3(NCH, 2), 256>>>(A, C, E, G);
    phaseA_kernel<<<dim3(BATCH/256, NCH, 2), 256>>>(U, A, B, C, D, E, F, G, bias, out);
    phaseB_kernel<<<1024, 256>>>();
    fixup_kernel<<<dim3(BATCH/256, NCH), 256>>>(out);
}

// round 3
// speedup vs baseline: 1.9633x; 1.0012x over previous
#include <cuda_runtime.h>
#include <cstdint>

#define BATCH 4096
#define NST   512
#define IO    16
#define DS    32
#define PTOT  8192
#define NCH   32
#define LCH   16   // stages per chunk

// ---------------- scratch (device globals; no mallocs allowed) ----------------
__device__ float g_xloc[2][BATCH][NCH][DS];   // local chunk-exit states
__device__ float g_xin [2][BATCH][NCH][DS];   // chunk-entry states
__device__ float g_M   [2][NST][IO*DS];       // M_k = C_k Phi_k ; N_k = G_k Psi_k
__device__ float g_P   [2][NCH][DS*DS];       // chunk propagators
__device__ float g_ya  [BATCH*PTOT];          // anticausal local y

// ---------------- cp.async helpers ----------------
__device__ __forceinline__ void cpasync16(void* s, const void* g) {
    uint32_t sa = (uint32_t)__cvta_generic_to_shared(s);
    asm volatile("cp.async.cg.shared.global [%0], [%1], 16;" :: "r"(sa), "l"(g));
}
__device__ __forceinline__ void cpcommit() { asm volatile("cp.async.commit_group;"); }
template<int N> __device__ __forceinline__ void cpwait() {
    asm volatile("cp.async.wait_group %0;" :: "n"(N));
}

// =====================================================================
// Precompute: per (dir, chunk): prefix transfer matrices + M/N + P.
//   causal:  Phi_{c0}=I; M_k=C_k Phi; Phi<-A_k Phi;  P_c = final Phi
//   anti:    Psi_{top}=I; N_k=G_k Psi; Psi<-E_k Psi; P^a_c = final Psi
// =====================================================================
__global__ void precompute_kernel(const float* __restrict__ A, const float* __restrict__ C,
                                  const float* __restrict__ E, const float* __restrict__ G) {
    __shared__ float Phi[2][DS*DS];
    const int tid = threadIdx.x;
    const int c = blockIdx.x, d = blockIdx.y;

    for (int i = tid; i < DS*DS; i += 256) Phi[0][i] = ((i >> 5) == (i & 31)) ? 1.f : 0.f;
    __syncthreads();

    int pb = 0;
    for (int t = 0; t < LCH; ++t) {
        const int k = (d == 0) ? (c*LCH + t) : (c*LCH + LCH-1 - t);
        const float* W1 = (d == 0) ? (C + k*IO*DS) : (G + k*IO*DS);   // 16x32
        const float* W2 = (d == 0) ? (A + k*DS*DS) : (E + k*DS*DS);   // 32x32

        // M_k = W1 * Phi  (512 outputs, 2 per thread)
        float* Mk = &g_M[d][k][0];
        for (int e = tid; e < IO*DS; e += 256) {
            const int i = e >> 5, j = e & 31;
            float acc = 0.f;
#pragma unroll
            for (int l = 0; l < DS; ++l) acc += W1[i*DS + l] * Phi[pb][l*DS + j];
            Mk[e] = acc;
        }
        // Phi_new = W2 * Phi  (1024 outputs, 4 per thread)
        for (int e = tid; e < DS*DS; e += 256) {
            const int i = e >> 5, j = e & 31;
            float acc = 0.f;
#pragma unroll
            for (int l = 0; l < DS; ++l) acc += W2[i*DS + l] * Phi[pb][l*DS + j];
            Phi[pb^1][e] = acc;
        }
        __syncthreads();
        pb ^= 1;
    }
    for (int e = tid; e < DS*DS; e += 256) g_P[d][c][e] = Phi[pb][e];
}

// =====================================================================
// Phase A: local chunk scans with zero initial state. One thread per row.
// CTA = (rowblock of 256, chunk, dir). Weights double-buffered via cp.async.
// =====================================================================
#define CSZ 2320   // causal stage floats: A 0..1024, B 1024..1536, C 1536..2048, D 2048..2304, bias 2304..2320
#define ASZ 2048   // anti stage floats:   E 0..1024, F 1024..1536, G 1536..2048

__global__ __launch_bounds__(256, 2)
void phaseA_kernel(const float* __restrict__ U,
                   const float* __restrict__ A, const float* __restrict__ B,
                   const float* __restrict__ C, const float* __restrict__ D,
                   const float* __restrict__ E, const float* __restrict__ F,
                   const float* __restrict__ G, const float* __restrict__ bias,
                   float* __restrict__ out) {
    __shared__ float sw[2][CSZ];

    const int tid = threadIdx.x;
    const int c = blockIdx.y, d = blockIdx.z;
    const int row = blockIdx.x * 256 + tid;
    const int k0 = c * LCH;

    auto load_stage = [&](float* dst, int k) {
        if (d == 0) {
            for (int i = tid; i < 580; i += 256) {
                const float4* src;
                if      (i < 256) src = (const float4*)(A + (size_t)k*1024) + i;
                else if (i < 384) src = (const float4*)(B + (size_t)k*512)  + (i-256);
                else if (i < 512) src = (const float4*)(C + (size_t)k*512)  + (i-384);
                else if (i < 576) src = (const float4*)(D + (size_t)k*256)  + (i-512);
                else              src = (const float4*)(bias + (size_t)k*16) + (i-576);
                cpasync16((float4*)dst + i, src);
            }
        } else {
            for (int i = tid; i < 512; i += 256) {
                const float4* src;
                if      (i < 256) src = (const float4*)(E + (size_t)k*1024) + i;
                else if (i < 384) src = (const float4*)(F + (size_t)k*512)  + (i-256);
                else              src = (const float4*)(G + (size_t)k*512)  + (i-384);
                cpasync16((float4*)dst + i, src);
            }
        }
    };
    auto stage_k = [&](int t) { return (d == 0) ? (k0 + t) : (k0 + LCH-1 - t); };

    load_stage(sw[0], stage_k(0)); cpcommit();
    load_stage(sw[1], stage_k(1)); cpcommit();

    float x[DS];
#pragma unroll
    for (int i = 0; i < DS; ++i) x[i] = 0.f;

#pragma unroll 1
    for (int t = 0; t < LCH; ++t) {
        cpwait<1>();
        __syncthreads();
        const float* w = sw[t & 1];
        const int k = stage_k(t);
        const size_t off = (size_t)row * PTOT + (size_t)k * IO;

        float u[IO];
        {
            const float4* up = (const float4*)(U + off);
#pragma unroll
            for (int m = 0; m < 4; ++m) {
                float4 v = up[m];
                u[4*m] = v.x; u[4*m+1] = v.y; u[4*m+2] = v.z; u[4*m+3] = v.w;
            }
        }

        if (d == 0) {
            // y = C x + D u + bias
            float y[IO];
#pragma unroll
            for (int i = 0; i < IO; ++i) {
                float acc = w[2304 + i];
#pragma unroll
                for (int j = 0; j < 8; ++j) {
                    float4 cv = ((const float4*)(w + 1536))[i*8 + j];
                    acc += cv.x*x[4*j] + cv.y*x[4*j+1] + cv.z*x[4*j+2] + cv.w*x[4*j+3];
                }
#pragma unroll
                for (int j = 0; j < 4; ++j) {
                    float4 dv = ((const float4*)(w + 2048))[i*4 + j];
                    acc += dv.x*u[4*j] + dv.y*u[4*j+1] + dv.z*u[4*j+2] + dv.w*u[4*j+3];
                }
                y[i] = acc;
            }
            float4* op = (float4*)(out + off);
#pragma unroll
            for (int m = 0; m < 4; ++m)
                op[m] = make_float4(y[4*m], y[4*m+1], y[4*m+2], y[4*m+3]);

            // x' = A x + B u
            float xn[DS];
#pragma unroll
            for (int i = 0; i < DS; ++i) {
                float acc = 0.f;
#pragma unroll
                for (int j = 0; j < 8; ++j) {
                    float4 av = ((const float4*)w)[i*8 + j];
                    acc += av.x*x[4*j] + av.y*x[4*j+1] + av.z*x[4*j+2] + av.w*x[4*j+3];
                }
#pragma unroll
                for (int j = 0; j < 4; ++j) {
                    float4 bv = ((const float4*)(w + 1024))[i*4 + j];
                    acc += bv.x*u[4*j] + bv.y*u[4*j+1] + bv.z*u[4*j+2] + bv.w*u[4*j+3];
                }
                xn[i] = acc;
            }
#pragma unroll
            for (int i = 0; i < DS; ++i) x[i] = xn[i];
        } else {
            // y = G z (z before update)
            float y[IO];
#pragma unroll
            for (int i = 0; i < IO; ++i) {
                float acc = 0.f;
#pragma unroll
                for (int j = 0; j < 8; ++j) {
                    float4 gv = ((const float4*)(w + 1536))[i*8 + j];
                    acc += gv.x*x[4*j] + gv.y*x[4*j+1] + gv.z*x[4*j+2] + gv.w*x[4*j+3];
                }
                y[i] = acc;
            }
            float4* op = (float4*)(g_ya + off);
#pragma unroll
            for (int m = 0; m < 4; ++m)
                op[m] = make_float4(y[4*m], y[4*m+1], y[4*m+2], y[4*m+3]);

            // z' = E z + F u
            float xn[DS];
#pragma unroll
            for (int i = 0; i < DS; ++i) {
                float acc = 0.f;
#pragma unroll
                for (int j = 0; j < 8; ++j) {
                    float4 ev = ((const float4*)w)[i*8 + j];
                    acc += ev.x*x[4*j] + ev.y*x[4*j+1] + ev.z*x[4*j+2] + ev.w*x[4*j+3];
                }
#pragma unroll
                for (int j = 0; j < 4; ++j) {
                    float4 fv = ((const float4*)(w + 1024))[i*4 + j];
                    acc += fv.x*u[4*j] + fv.y*u[4*j+1] + fv.z*u[4*j+2] + fv.w*u[4*j+3];
                }
                xn[i] = acc;
            }
#pragma unroll
            for (int i = 0; i < DS; ++i) x[i] = xn[i];
        }

        __syncthreads();
        if (t + 2 < LCH) load_stage(sw[t & 1], stage_k(t + 2));
        cpcommit();
    }

    // store chunk-exit local state
    float4* xo = (float4*)&g_xloc[d][row][c][0];
#pragma unroll
    for (int m = 0; m < 8; ++m)
        xo[m] = make_float4(x[4*m], x[4*m+1], x[4*m+2], x[4*m+3]);
}

// =====================================================================
// Phase B: sequential chunk recombination per row. One warp per (row, dir).
//   x_in(first)=0; store x_in(c); x_in(next) = P_c x_in(c) + xloc(c)
// =====================================================================
__global__ __launch_bounds__(256)
void phaseB_kernel() {
    __shared__ float sP[DS*DS];
    const int tid = threadIdx.x, lane = tid & 31, wp = tid >> 5;
    const int d = blockIdx.x >> 9;                  // 512 CTAs per direction
    const int row = ((blockIdx.x & 511) << 3) + wp;

    float x = 0.f;
    for (int ci = 0; ci < NCH; ++ci) {
        const int c = (d == 0) ? ci : (NCH-1 - ci);
        __syncthreads();
        for (int i = tid; i < DS*DS; i += 256) sP[i] = g_P[d][c][i];
        __syncthreads();

        g_xin[d][row][c][lane] = x;
        float acc = g_xloc[d][row][c][lane];
        const float* pr = &sP[lane * DS];
#pragma unroll
        for (int j = 0; j < DS; ++j) {
            const int jj = (j + lane) & 31;          // bank-conflict-free stagger
            acc += pr[jj] * __shfl_sync(0xffffffffu, x, jj);
        }
        x = acc;
    }
}

// =====================================================================
// Fixup: out = y_c(+bias) + y_a_local + M_k x_in + N_k z_in
// CTA = (rowblock 256, chunk); M/N double-buffered via cp.async.
// =====================================================================
__global__ __launch_bounds__(256, 2)
void fixup_kernel(float* __restrict__ out) {
    __shared__ float sm[2][2*IO*DS];   // M_k (512) | N_k (512)
    const int tid = threadIdx.x;
    const int c = blockIdx.y;
    const int row = blockIdx.x * 256 + tid;
    const int k0 = c * LCH;

    auto load_mn = [&](float* dst, int k) {
        if (tid < 128) cpasync16((float4*)dst + tid, (const float4*)&g_M[0][k][0] + tid);
        else           cpasync16((float4*)dst + tid, (const float4*)&g_M[1][k][0] + (tid-128));
    };
    load_mn(sm[0], k0);     cpcommit();
    load_mn(sm[1], k0 + 1); cpcommit();

    float xin[DS], zin[DS];
    {
        const float4* xi = (const float4*)&g_xin[0][row][c][0];
        const float4* zi = (const float4*)&g_xin[1][row][c][0];
#pragma unroll
        for (int m = 0; m < 8; ++m) {
            float4 a = xi[m]; xin[4*m]=a.x; xin[4*m+1]=a.y; xin[4*m+2]=a.z; xin[4*m+3]=a.w;
            float4 b = zi[m]; zin[4*m]=b.x; zin[4*m+1]=b.y; zin[4*m+2]=b.z; zin[4*m+3]=b.w;
        }
    }

#pragma unroll 1
    for (int s = 0; s < LCH; ++s) {
        cpwait<1>();
        __syncthreads();
        const float* M = sm[s & 1];
        const float* N = M + IO*DS;
        const int k = k0 + s;
        const size_t off = (size_t)row * PTOT + (size_t)k * IO;

        float y[IO];
        {
            const float4* op = (const float4*)(out + off);
            const float4* ap = (const float4*)(g_ya + off);
#pragma unroll
            for (int m = 0; m < 4; ++m) {
                float4 a = op[m], b = ap[m];
                y[4*m]=a.x+b.x; y[4*m+1]=a.y+b.y; y[4*m+2]=a.z+b.z; y[4*m+3]=a.w+b.w;
            }
        }
#pragma unroll
        for (int i = 0; i < IO; ++i) {
            float acc = y[i];
#pragma unroll
            for (int j = 0; j < 8; ++j) {
                float4 mv = ((const float4*)M)[i*8 + j];
                acc += mv.x*xin[4*j] + mv.y*xin[4*j+1] + mv.z*xin[4*j+2] + mv.w*xin[4*j+3];
                float4 nv = ((const float4*)N)[i*8 + j];
                acc += nv.x*zin[4*j] + nv.y*zin[4*j+1] + nv.z*zin[4*j+2] + nv.w*zin[4*j+3];
            }
            y[i] = acc;
        }
        float4* op = (float4*)(out + off);
#pragma unroll
        for (int m = 0; m < 4; ++m)
            op[m] = make_float4(y[4*m], y[4*m+1], y[4*m+2], y[4*m+3]);

        __syncthreads();
        if (s + 2 < LCH) load_mn(sm[s & 1], k0 + s + 2);
        cpcommit();
    }
}

// =====================================================================
extern "C" void kernel_launch(void* const* d_in, const int* in_sizes, int n_in,
                              void* d_out, int out_size) {
    const float* U    = (const float*)d_in[0];
    const float* A    = (const float*)d_in[1];
    const float* B    = (const float*)d_in[2];
    const float* C    = (const float*)d_in[3];
    const float* D    = (const float*)d_in[4];
    const float* E    = (const float*)d_in[5];
    const float* F    = (const float*)d_in[6];
    const float* G    = (const float*)d_in[7];
    const float* bias = (const float*)d_in[8];
    float* out = (float*)d_out;

    precompute_kernel<<<dim3(NCH, 2), 256>>>(A, C, E, G);
    phaseA_kernel<<<dim3(BATCH/256, NCH, 2), 256>>>(U, A, B, C, D, E, F, G, bias, out);
    phaseB_kernel<<<1024, 256>>>();
    fixup_kernel<<<dim3(BATCH/256, NCH), 256>>>(out);
}